// round 8
// baseline (speedup 1.0000x reference)
#include <cuda_runtime.h>
#include <cstdint>

#define DINLINE __device__ __forceinline__

// ---------------- geometry ----------------
#define NWARP 8
#define NTHR  256
#define WROWS 48
#define DTILE (NWARP * WROWS)   // 384 edges per tile
#define KDIM  256
#define HDIM  64
#define RING  3                 // cp.async ring slots per warp
#define CHUNK_B 6144            // 48 rows x 32 cols x 4B
#define NCHUNK 8                // chunks per tile (32 cols each)
#define PREF  2                 // chunks committed ahead

// ---------------- smem layout ----------------
#define OFF_W1F  0                       // 32kt x 4p x 32 lanes x float4 = 65536
#define OFF_W2F  65536                   // 8kt x 4p x 32 x float4 = 16384
#define OFF_CMB  81920                   // 8 warps x RING x CHUNK_B = 147456
#define OFF_B1   229376                  // 256B
#define OFF_B2   229632                  // 256B
#define OFF_FLAG 229888                  // 4B
#define SMEM_TOTAL 229952                // < 232448

// ---------------- helpers ----------------
DINLINE float tf32r(float x) {   // round fp32 -> tf32 (rna), keep as fp32 bits
    uint32_t u;
    asm("cvt.rna.tf32.f32 %0, %1;" : "=r"(u) : "f"(x));
    return __uint_as_float(u);
}

DINLINE uint32_t s2u(const void* p) {
    uint32_t a;
    asm("{ .reg .u64 t; cvta.to.shared.u64 t, %1; cvt.u32.u64 %0, t; }" : "=r"(a) : "l"(p));
    return a;
}

DINLINE void cp16(uint32_t dst, const void* src) {
    asm volatile("cp.async.cg.shared.global [%0], [%1], 16;" :: "r"(dst), "l"(src));
}
DINLINE void cp_commit() { asm volatile("cp.async.commit_group;" ::: "memory"); }
template <int N> DINLINE void cp_wait() {
    asm volatile("cp.async.wait_group %0;" :: "n"(N) : "memory");
}

// D += A(m16k8,row) * B(k8n8,col), tf32 in / f32 out
DINLINE void mma8(float* c, uint32_t a0, uint32_t a1, uint32_t a2, uint32_t a3,
                  uint32_t b0, uint32_t b1) {
    asm volatile(
        "mma.sync.aligned.m16n8k8.row.col.f32.tf32.tf32.f32 "
        "{%0,%1,%2,%3}, {%4,%5,%6,%7}, {%8,%9}, {%0,%1,%2,%3};"
        : "+f"(c[0]), "+f"(c[1]), "+f"(c[2]), "+f"(c[3])
        : "r"(a0), "r"(a1), "r"(a2), "r"(a3), "r"(b0), "r"(b1));
}

DINLINE void mma8f(float* c, uint32_t a0, uint32_t a1, uint32_t a2, uint32_t a3,
                   float b0, float b1) {
    mma8(c, a0, a1, a2, a3, __float_as_uint(b0), __float_as_uint(b1));
}

// ---------------- per-warp chunk issue ----------------
// chunk c of a tile: 48 warp-rows x 32 cols [c*32, c*32+32).
// c>>1 selects tensor (src|dest|ea|u), (c&1)*32 the col offset within it.
// smem: row stride 128B, float4 quad q stored at q ^ (row&7).
DINLINE void issue_chunk(uint32_t slot, long ebase, int E, int c, int lane,
                         const float* __restrict__ s0, const float* __restrict__ s1,
                         const float* __restrict__ s2, const float* __restrict__ u,
                         const void* __restrict__ bat, int is64) {
    const int tensor = c >> 1;
    const int q = lane & 7;
    const int coloff = (c & 1) * 32 + q * 4;
    const int rbase = lane >> 3;                 // 0..3
#pragma unroll
    for (int it = 0; it < 12; it++) {
        int row = it * 4 + rbase;
        long e = ebase + row; if (e >= E) e = E - 1;
        const float* p;
        if (tensor == 0)      p = s0 + e * 64 + coloff;
        else if (tensor == 1) p = s1 + e * 64 + coloff;
        else if (tensor == 2) p = s2 + e * 64 + coloff;
        else {
            long b = is64 ? (long)((const long long*)bat)[e]
                          : (long)((const int*)bat)[e];
            p = u + b * 64 + coloff;
        }
        cp16(slot + (uint32_t)(row * 128) + (uint32_t)((q ^ (row & 7)) << 4), p);
    }
}

// ---------------- kernel ----------------
__global__ void __launch_bounds__(NTHR, 1)
megnet_edge_kernel(const float* __restrict__ src, const float* __restrict__ dst,
                   const float* __restrict__ ea,  const float* __restrict__ u,
                   const int* __restrict__ bat,
                   const float* __restrict__ W1, const float* __restrict__ b1,
                   const float* __restrict__ W2, const float* __restrict__ b2,
                   float* __restrict__ out, int E, int NT) {
    extern __shared__ char smem[];
    const uint32_t sb = s2u(smem);
    const int tid = threadIdx.x;
    const int w = tid >> 5;
    const int lane = tid & 31;

    // ---- one-time: pack W1/W2 into paired mma B-fragments (tf32 rna) ----
    // slot s: lane = s&31, p = (s>>5)&3, kt = s>>7.
    // float4 = {W[k][n2p], W[k+4][n2p], W[k][n2p1], W[k+4][n2p1]}
    //   k = kt*8 + (l&3), n2p = p*16 + (l>>2), n2p1 = n2p + 8
    for (int s = tid; s < 4096; s += NTHR) {
        int l = s & 31, p = (s >> 5) & 3, kt = s >> 7;
        int k = kt * 8 + (l & 3), n0 = p * 16 + (l >> 2);
        float4 v = make_float4(tf32r(W1[k * 64 + n0]),       tf32r(W1[(k + 4) * 64 + n0]),
                               tf32r(W1[k * 64 + n0 + 8]),   tf32r(W1[(k + 4) * 64 + n0 + 8]));
        *(float4*)(smem + OFF_W1F + (size_t)s * 16) = v;
    }
    for (int s = tid; s < 1024; s += NTHR) {
        int l = s & 31, p = (s >> 5) & 3, kt = s >> 7;
        int k = kt * 8 + (l & 3), n0 = p * 16 + (l >> 2);
        float4 v = make_float4(tf32r(W2[k * 64 + n0]),       tf32r(W2[(k + 4) * 64 + n0]),
                               tf32r(W2[k * 64 + n0 + 8]),   tf32r(W2[(k + 4) * 64 + n0 + 8]));
        *(float4*)(smem + OFF_W2F + (size_t)s * 16) = v;
    }
    if (tid < 64) {
        ((float*)(smem + OFF_B1))[tid] = b1[tid];
        ((float*)(smem + OFF_B2))[tid] = b2[tid];
    }
    if (tid == 0) {
        // batch dtype sniff: int64 payload (values < 2^31) has all-zero odd words
        int is64 = 1;
        for (int i = 1; i < 32; i += 2)
            if (bat[i] != 0) { is64 = 0; break; }
        *(int*)(smem + OFF_FLAG) = is64;
    }
    __syncthreads();
    const int is64 = *(const int*)(smem + OFF_FLAG);
    const float* b1s = (const float*)(smem + OFF_B1);
    const float* b2s = (const float*)(smem + OFF_B2);

    // ---- per-warp constants ----
    const int r0 = lane >> 2;                    // 0..7
    const int l3 = lane & 3;
    const uint32_t ringbase = sb + OFF_CMB + (uint32_t)w * (RING * CHUNK_B);
    const int srcL0 = (lane & 28) | (l3 >> 1);   // shfl owner for cols l3
    const int srcL1 = srcL0 + 2;                 // owner for cols l3+4
    const bool hi = (l3 & 1) != 0;

    const int bid = blockIdx.x, grid = gridDim.x;
    const int numT = (NT - bid + grid - 1) / grid;
    const long total = (long)numT * NCHUNK;

    float C[96];                                 // [m(3)][nt(8)][4]

    // prologue: PREF chunks ahead
#pragma unroll
    for (int pc = 0; pc < PREF; pc++) {
        if (pc < total) {
            issue_chunk(ringbase + (uint32_t)(pc % RING) * CHUNK_B,
                        (long)bid * DTILE + w * WROWS, E, pc, lane,
                        src, dst, ea, u, bat, is64);
        }
        cp_commit();   // commit even if empty to keep group count in sync
    }

    for (long n = 0; n < total; n++) {
        const int c = (int)(n & (NCHUNK - 1));
        const long tile = bid + (n >> 3) * grid;

        if (n + PREF < total) {
            long np = n + PREF;
            issue_chunk(ringbase + (uint32_t)(np % RING) * CHUNK_B,
                        (bid + (np >> 3) * grid) * DTILE + w * WROWS, E,
                        (int)(np & (NCHUNK - 1)), lane,
                        src, dst, ea, u, bat, is64);
            cp_commit();
        }
        cp_wait<PREF>();          // chunk n landed (PREF groups may remain)
        __syncwarp();

        if (c == 0) {
#pragma unroll
            for (int i = 0; i < 96; i++) C[i] = 0.f;
        }

        // ---------- layer-1 partial: 4 k-groups of this chunk ----------
        const char* sbase = smem + OFF_CMB + (size_t)w * (RING * CHUNK_B)
                                 + (size_t)(n % RING) * CHUNK_B;
#pragma unroll
        for (int kg = 0; kg < 4; kg++) {
            const int ktg = c * 4 + kg;
            const uint32_t x0 = (uint32_t)((((2 * kg) ^ r0) << 4) + l3 * 4);
            uint32_t a[3][4];
#pragma unroll
            for (int m = 0; m < 3; m++) {
                const char* rb = sbase + (m * 16 + r0) * 128;
                a[m][0] = *(const uint32_t*)(rb + x0);
                a[m][1] = *(const uint32_t*)(rb + 1024 + x0);
                a[m][2] = *(const uint32_t*)(rb + (x0 ^ 16));
                a[m][3] = *(const uint32_t*)(rb + 1024 + (x0 ^ 16));
            }
            const char* wf = smem + OFF_W1F + (size_t)ktg * 2048 + (size_t)lane * 16;
#pragma unroll
            for (int p = 0; p < 4; p++) {
                float4 bv = *(const float4*)(wf + p * 512);
#pragma unroll
                for (int m = 0; m < 3; m++) {
                    float* Cp = C + m * 32 + p * 8;
                    mma8f(Cp,     a[m][0], a[m][1], a[m][2], a[m][3], bv.x, bv.y);
                    mma8f(Cp + 4, a[m][0], a[m][1], a[m][2], a[m][3], bv.z, bv.w);
                }
            }
        }

        if (c != NCHUNK - 1) continue;

        // ---------- h = relu(C + b1), tf32 round (in place) ----------
#pragma unroll
        for (int m = 0; m < 3; m++) {
#pragma unroll
            for (int nt = 0; nt < 8; nt++) {
                float2 bb = *(const float2*)(b1s + nt * 8 + 2 * l3);
                float* Cm = C + m * 32 + nt * 4;
                Cm[0] = tf32r(fmaxf(Cm[0] + bb.x, 0.f));
                Cm[1] = tf32r(fmaxf(Cm[1] + bb.y, 0.f));
                Cm[2] = tf32r(fmaxf(Cm[2] + bb.x, 0.f));
                Cm[3] = tf32r(fmaxf(Cm[3] + bb.y, 0.f));
            }
        }

        // ---------- layer 2: A from C via intra-quad shuffles ----------
        // n-half at a time; each W2 fragment load shared by all 3 m-subs.
        const long e0 = tile * DTILE + w * WROWS + r0;
#pragma unroll
        for (int nh = 0; nh < 2; nh++) {
            float C2[48];                        // [m(3)][ntl(4)][4]
#pragma unroll
            for (int i = 0; i < 48; i++) C2[i] = 0.f;
#pragma unroll
            for (int kt = 0; kt < 8; kt++) {
                const char* wf = smem + OFF_W2F + (size_t)kt * 2048
                                     + (size_t)nh * 1024 + (size_t)lane * 16;
                float4 bv0 = *(const float4*)(wf);
                float4 bv1 = *(const float4*)(wf + 512);
#pragma unroll
                for (int m = 0; m < 3; m++) {
                    const float* h = C + m * 32 + kt * 4;
                    float v00 = __shfl_sync(0xffffffffu, h[0], srcL0);
                    float v01 = __shfl_sync(0xffffffffu, h[1], srcL0);
                    float v02 = __shfl_sync(0xffffffffu, h[2], srcL0);
                    float v03 = __shfl_sync(0xffffffffu, h[3], srcL0);
                    float v10 = __shfl_sync(0xffffffffu, h[0], srcL1);
                    float v11 = __shfl_sync(0xffffffffu, h[1], srcL1);
                    float v12 = __shfl_sync(0xffffffffu, h[2], srcL1);
                    float v13 = __shfl_sync(0xffffffffu, h[3], srcL1);
                    uint32_t a0 = __float_as_uint(hi ? v01 : v00);
                    uint32_t a1 = __float_as_uint(hi ? v03 : v02);
                    uint32_t a2 = __float_as_uint(hi ? v11 : v10);
                    uint32_t a3 = __float_as_uint(hi ? v13 : v12);
                    float* Cm = C2 + m * 16;
                    mma8f(Cm,      a0, a1, a2, a3, bv0.x, bv0.y);
                    mma8f(Cm + 4,  a0, a1, a2, a3, bv0.z, bv0.w);
                    mma8f(Cm + 8,  a0, a1, a2, a3, bv1.x, bv1.y);
                    mma8f(Cm + 12, a0, a1, a2, a3, bv1.z, bv1.w);
                }
            }

            // ---------- out = relu(C2 + b2) -> gmem ----------
#pragma unroll
            for (int m = 0; m < 3; m++) {
                const long e = e0 + m * 16;
#pragma unroll
                for (int ntl = 0; ntl < 4; ntl++) {
                    const int col0 = (nh * 4 + ntl) * 8 + 2 * l3;
                    float2 bb = *(const float2*)(b2s + col0);
                    const float* Cm = C2 + m * 16 + ntl * 4;
                    if (e < E) {
                        float2 v = make_float2(fmaxf(Cm[0] + bb.x, 0.f),
                                               fmaxf(Cm[1] + bb.y, 0.f));
                        *(float2*)(out + e * 64 + col0) = v;
                    }
                    if (e + 8 < E) {
                        float2 v = make_float2(fmaxf(Cm[2] + bb.x, 0.f),
                                               fmaxf(Cm[3] + bb.y, 0.f));
                        *(float2*)(out + (e + 8) * 64 + col0) = v;
                    }
                }
            }
        }
    }
}

// ---------------- launch ----------------
extern "C" void kernel_launch(void* const* d_in, const int* in_sizes, int n_in,
                              void* d_out, int out_size) {
    const float* src = (const float*)d_in[0];
    const float* dst = (const float*)d_in[1];
    const float* ea  = (const float*)d_in[2];
    const float* u   = (const float*)d_in[3];
    const int*   bat = (const int*)d_in[4];   // int32 or int64 payload; sniffed in-kernel
    const float* W1  = (const float*)d_in[5];
    const float* b1  = (const float*)d_in[6];
    const float* W2  = (const float*)d_in[7];
    const float* b2  = (const float*)d_in[8];
    float* out = (float*)d_out;

    int E  = in_sizes[0] / 64;
    int NT = (E + DTILE - 1) / DTILE;

    int dev = 0;
    cudaGetDevice(&dev);
    int nsm = 148;
    cudaDeviceGetAttribute(&nsm, cudaDevAttrMultiProcessorCount, dev);
    int grid = (NT < nsm) ? NT : nsm;

    cudaFuncSetAttribute(megnet_edge_kernel,
                         cudaFuncAttributeMaxDynamicSharedMemorySize, SMEM_TOTAL);
    megnet_edge_kernel<<<grid, NTHR, SMEM_TOTAL>>>(src, dst, ea, u, bat,
                                                   W1, b1, W2, b2, out, E, NT);
    (void)n_in; (void)out_size;
}

// round 9
// speedup vs baseline: 1.9066x; 1.9066x over previous
#include <cuda_runtime.h>
#include <cstdint>

#define DINLINE __device__ __forceinline__

// ---------------- geometry ----------------
#define NWARP 8
#define NTHR  256
#define WROWS 32
#define DTILE (NWARP * WROWS)   // 256 edges per tile
#define RING  4                 // cp.async ring slots per warp
#define CHUNK_B 4096            // 32 rows x 32 cols x 4B
#define NCHUNK 8                // chunks per tile (32 cols each)
#define PREF  3                 // chunks committed ahead

// ---------------- smem layout ----------------
#define OFF_W1F  0                       // 16ktf x 4np x 32 lanes x 16B = 32768
#define OFF_W2F  32768                   // 4ktf x 4np x 32 x 16B = 8192
#define OFF_CMB  40960                   // 8 warps x RING x CHUNK_B = 131072
#define OFF_B1   172032                  // 256B
#define OFF_B2   172288                  // 256B
#define OFF_FLAG 172544                  // 4B
#define SMEM_TOTAL 172608                // < 232448

// ---------------- helpers ----------------
DINLINE uint32_t s2u(const void* p) {
    uint32_t a;
    asm("{ .reg .u64 t; cvta.to.shared.u64 t, %1; cvt.u32.u64 %0, t; }" : "=r"(a) : "l"(p));
    return a;
}

// pack two fp32 -> f16x2 (lo = first arg, hi = second)
DINLINE uint32_t f2h2(float lo, float hi) {
    uint32_t r;
    asm("cvt.rn.f16x2.f32 %0, %1, %2;" : "=r"(r) : "f"(hi), "f"(lo));
    return r;
}

DINLINE void cp16(uint32_t dst, const void* src) {
    asm volatile("cp.async.cg.shared.global [%0], [%1], 16;" :: "r"(dst), "l"(src));
}
DINLINE void cp_commit() { asm volatile("cp.async.commit_group;" ::: "memory"); }
template <int N> DINLINE void cp_wait() {
    asm volatile("cp.async.wait_group %0;" :: "n"(N) : "memory");
}

// D += A(m16k16,row,f16) * B(k16n8,col,f16), fp32 accumulate
DINLINE void mmaf16(float* c, uint32_t a0, uint32_t a1, uint32_t a2, uint32_t a3,
                    uint32_t b0, uint32_t b1) {
    asm volatile(
        "mma.sync.aligned.m16n8k16.row.col.f32.f16.f16.f32 "
        "{%0,%1,%2,%3}, {%4,%5,%6,%7}, {%8,%9}, {%0,%1,%2,%3};"
        : "+f"(c[0]), "+f"(c[1]), "+f"(c[2]), "+f"(c[3])
        : "r"(a0), "r"(a1), "r"(a2), "r"(a3), "r"(b0), "r"(b1));
}

// ---------------- per-warp chunk issue (fp32 comb, proven R5 scheme) ----------------
// chunk c of a tile: 32 warp-rows x 32 cols [c*32, c*32+32).
// c>>1 selects tensor (src|dest|ea|u), (c&1)*32 the col offset within it.
// smem: row stride 128B, float4 quad q stored at q ^ (row&7).
DINLINE void issue_chunk(uint32_t slot, long ebase, int E, int c, int lane,
                         const float* __restrict__ s0, const float* __restrict__ s1,
                         const float* __restrict__ s2, const float* __restrict__ u,
                         const void* __restrict__ bat, int is64) {
    const int tensor = c >> 1;
    const int coloff = (c & 1) * 32;
#pragma unroll
    for (int i = 0; i < 8; i++) {
        int flat = i * 32 + lane;
        int row = flat >> 3, q = flat & 7;
        long e = ebase + row; if (e >= E) e = E - 1;
        const float* p;
        if (tensor == 0)      p = s0 + e * 64 + coloff + q * 4;
        else if (tensor == 1) p = s1 + e * 64 + coloff + q * 4;
        else if (tensor == 2) p = s2 + e * 64 + coloff + q * 4;
        else {
            long b = is64 ? (long)((const long long*)bat)[e]
                          : (long)((const int*)bat)[e];
            p = u + b * 64 + coloff + q * 4;
        }
        cp16(slot + (uint32_t)(row * 128) + (uint32_t)((q ^ (row & 7)) << 4), p);
    }
}

// ---------------- kernel ----------------
__global__ void __launch_bounds__(NTHR, 1)
megnet_edge_kernel(const float* __restrict__ src, const float* __restrict__ dst,
                   const float* __restrict__ ea,  const float* __restrict__ u,
                   const int* __restrict__ bat,
                   const float* __restrict__ W1, const float* __restrict__ b1,
                   const float* __restrict__ W2, const float* __restrict__ b2,
                   float* __restrict__ out, int E, int NT) {
    extern __shared__ char smem[];
    const uint32_t sb = s2u(smem);
    const int tid = threadIdx.x;
    const int w = tid >> 5;
    const int lane = tid & 31;

    // ---- one-time: pack W1/W2 into fp16 m16n8k16 B-fragments ----
    // slot s: lane = s&31, np = (s>>5)&3, ktf = s>>7
    // uint4 = {b0(nt=2np), b1(nt=2np), b0(nt=2np+1), b1(nt=2np+1)}
    //   b0 = {W[kb][n], W[kb+1][n]}, b1 = {W[kb+8][n], W[kb+9][n]}
    //   kb = 16*ktf + 2*(l&3), n = 8*nt + (l>>2)
    for (int s = tid; s < 2048; s += NTHR) {
        int l = s & 31, np = (s >> 5) & 3, ktf = s >> 7;
        int g = l >> 2, t = l & 3;
        int kb = ktf * 16 + 2 * t;
        int n0 = (2 * np) * 8 + g, n1 = n0 + 8;
        uint4 v;
        v.x = f2h2(W1[kb * 64 + n0],       W1[(kb + 1) * 64 + n0]);
        v.y = f2h2(W1[(kb + 8) * 64 + n0], W1[(kb + 9) * 64 + n0]);
        v.z = f2h2(W1[kb * 64 + n1],       W1[(kb + 1) * 64 + n1]);
        v.w = f2h2(W1[(kb + 8) * 64 + n1], W1[(kb + 9) * 64 + n1]);
        *(uint4*)(smem + OFF_W1F + (size_t)s * 16) = v;
    }
    for (int s = tid; s < 512; s += NTHR) {
        int l = s & 31, np = (s >> 5) & 3, ktf = s >> 7;
        int g = l >> 2, t = l & 3;
        int kb = ktf * 16 + 2 * t;
        int n0 = (2 * np) * 8 + g, n1 = n0 + 8;
        uint4 v;
        v.x = f2h2(W2[kb * 64 + n0],       W2[(kb + 1) * 64 + n0]);
        v.y = f2h2(W2[(kb + 8) * 64 + n0], W2[(kb + 9) * 64 + n0]);
        v.z = f2h2(W2[kb * 64 + n1],       W2[(kb + 1) * 64 + n1]);
        v.w = f2h2(W2[(kb + 8) * 64 + n1], W2[(kb + 9) * 64 + n1]);
        *(uint4*)(smem + OFF_W2F + (size_t)s * 16) = v;
    }
    if (tid < 64) {
        ((float*)(smem + OFF_B1))[tid] = b1[tid];
        ((float*)(smem + OFF_B2))[tid] = b2[tid];
    }
    if (tid == 0) {
        // batch dtype sniff: int64 payload (values < 2^31) has all-zero odd words
        int is64 = 1;
        for (int i = 1; i < 32; i += 2)
            if (bat[i] != 0) { is64 = 0; break; }
        *(int*)(smem + OFF_FLAG) = is64;
    }
    __syncthreads();
    const int is64 = *(const int*)(smem + OFF_FLAG);
    const float* b1s = (const float*)(smem + OFF_B1);
    const float* b2s = (const float*)(smem + OFF_B2);

    // ---- per-warp constants ----
    const int g = lane >> 2;                     // fragment row 0..7
    const int t = lane & 3;
    const uint32_t ringbase = sb + OFF_CMB + (uint32_t)w * (RING * CHUNK_B);

    const int bid = blockIdx.x, grid = gridDim.x;
    const int numT = (NT - bid + grid - 1) / grid;
    const long total = (long)numT * NCHUNK;

    float C[64];                                 // [m(2)][nt(8)][4]

    // prologue: PREF chunks ahead
#pragma unroll
    for (int pc = 0; pc < PREF; pc++) {
        if (pc < total) {
            issue_chunk(ringbase + (uint32_t)(pc % RING) * CHUNK_B,
                        (long)bid * DTILE + w * WROWS, E, pc, lane,
                        src, dst, ea, u, bat, is64);
        }
        cp_commit();   // commit even if empty to keep group count in sync
    }

    for (long n = 0; n < total; n++) {
        const int c = (int)(n & (NCHUNK - 1));
        const long tile = bid + (n >> 3) * grid;

        if (n + PREF < total) {
            long np_ = n + PREF;
            issue_chunk(ringbase + (uint32_t)(np_ % RING) * CHUNK_B,
                        (bid + (np_ >> 3) * grid) * DTILE + w * WROWS, E,
                        (int)(np_ & (NCHUNK - 1)), lane,
                        src, dst, ea, u, bat, is64);
            cp_commit();
        }
        cp_wait<PREF>();          // chunk n landed (PREF groups may remain)
        __syncwarp();

        if (c == 0) {
#pragma unroll
            for (int i = 0; i < 64; i++) C[i] = 0.f;
        }

        // ---------- layer-1 partial: 2 k16-groups of this chunk ----------
        const char* sbase = smem + OFF_CMB + (size_t)w * (RING * CHUNK_B)
                                 + (size_t)(n % RING) * CHUNK_B;
#pragma unroll
        for (int kl = 0; kl < 2; kl++) {
            const int ktf = c * 2 + kl;
            // A fragments: fp32 pairs from smem -> f16x2
            const uint32_t q0 = (uint32_t)(4 * kl + (t >> 1));
            const uint32_t off0 = (((q0 ^ (uint32_t)g) << 4) + (uint32_t)((t & 1) * 8));
            const uint32_t off2 = ((((q0 + 2) ^ (uint32_t)g) << 4) + (uint32_t)((t & 1) * 8));
            uint32_t a[2][4];
#pragma unroll
            for (int m = 0; m < 2; m++) {
                const char* rb = sbase + (m * 16 + g) * 128;
                float2 v;
                v = *(const float2*)(rb + off0);        a[m][0] = f2h2(v.x, v.y);
                v = *(const float2*)(rb + 1024 + off0); a[m][1] = f2h2(v.x, v.y);
                v = *(const float2*)(rb + off2);        a[m][2] = f2h2(v.x, v.y);
                v = *(const float2*)(rb + 1024 + off2); a[m][3] = f2h2(v.x, v.y);
            }
            const char* wf = smem + OFF_W1F + (size_t)ktf * 2048 + (size_t)lane * 16;
#pragma unroll
            for (int np = 0; np < 4; np++) {
                uint4 bv = *(const uint4*)(wf + np * 512);
#pragma unroll
                for (int m = 0; m < 2; m++) {
                    float* Cp = C + m * 32 + np * 8;
                    mmaf16(Cp,     a[m][0], a[m][1], a[m][2], a[m][3], bv.x, bv.y);
                    mmaf16(Cp + 4, a[m][0], a[m][1], a[m][2], a[m][3], bv.z, bv.w);
                }
            }
        }

        if (c != NCHUNK - 1) continue;

        // ---------- tail: per m-sub, h = relu(C+b1) -> f16 A regs (no smem!) ----------
        const long e0 = tile * DTILE + w * WROWS + g;
#pragma unroll
        for (int m = 0; m < 2; m++) {
            // C-fragment (c0,c1,c2,c3) == fp16 A-fragment pair layout: direct cvt
            uint32_t ah[16];
#pragma unroll
            for (int nt = 0; nt < 8; nt++) {
                float2 bb = *(const float2*)(b1s + nt * 8 + 2 * t);
                const float* Cm = C + m * 32 + nt * 4;
                float h0 = fmaxf(Cm[0] + bb.x, 0.f);
                float h1 = fmaxf(Cm[1] + bb.y, 0.f);
                float h2v = fmaxf(Cm[2] + bb.x, 0.f);
                float h3 = fmaxf(Cm[3] + bb.y, 0.f);
                ah[nt * 2]     = f2h2(h0, h1);
                ah[nt * 2 + 1] = f2h2(h2v, h3);
            }

            // layer 2: C2[32] = h[16,64] @ W2  (A regs = ah quads)
            float C2[32];
#pragma unroll
            for (int i = 0; i < 32; i++) C2[i] = 0.f;
#pragma unroll
            for (int ktf = 0; ktf < 4; ktf++) {
                const char* wf = smem + OFF_W2F + (size_t)ktf * 2048 + (size_t)lane * 16;
#pragma unroll
                for (int np = 0; np < 4; np++) {
                    uint4 bv = *(const uint4*)(wf + np * 512);
                    mmaf16(C2 + np * 8,
                           ah[4 * ktf], ah[4 * ktf + 1], ah[4 * ktf + 2], ah[4 * ktf + 3],
                           bv.x, bv.y);
                    mmaf16(C2 + np * 8 + 4,
                           ah[4 * ktf], ah[4 * ktf + 1], ah[4 * ktf + 2], ah[4 * ktf + 3],
                           bv.z, bv.w);
                }
            }

            // out = relu(C2 + b2) -> gmem
            const long e = e0 + m * 16;
#pragma unroll
            for (int nt = 0; nt < 8; nt++) {
                const int col0 = nt * 8 + 2 * t;
                float2 bb = *(const float2*)(b2s + col0);
                const float* Cm = C2 + nt * 4;
                if (e < E) {
                    float2 v = make_float2(fmaxf(Cm[0] + bb.x, 0.f),
                                           fmaxf(Cm[1] + bb.y, 0.f));
                    *(float2*)(out + e * 64 + col0) = v;
                }
                if (e + 8 < E) {
                    float2 v = make_float2(fmaxf(Cm[2] + bb.x, 0.f),
                                           fmaxf(Cm[3] + bb.y, 0.f));
                    *(float2*)(out + (e + 8) * 64 + col0) = v;
                }
            }
        }
    }
}

// ---------------- launch ----------------
extern "C" void kernel_launch(void* const* d_in, const int* in_sizes, int n_in,
                              void* d_out, int out_size) {
    const float* src = (const float*)d_in[0];
    const float* dst = (const float*)d_in[1];
    const float* ea  = (const float*)d_in[2];
    const float* u   = (const float*)d_in[3];
    const int*   bat = (const int*)d_in[4];   // int32 or int64 payload; sniffed in-kernel
    const float* W1  = (const float*)d_in[5];
    const float* b1  = (const float*)d_in[6];
    const float* W2  = (const float*)d_in[7];
    const float* b2  = (const float*)d_in[8];
    float* out = (float*)d_out;

    int E  = in_sizes[0] / 64;
    int NT = (E + DTILE - 1) / DTILE;

    int dev = 0;
    cudaGetDevice(&dev);
    int nsm = 148;
    cudaDeviceGetAttribute(&nsm, cudaDevAttrMultiProcessorCount, dev);
    int grid = (NT < nsm) ? NT : nsm;

    cudaFuncSetAttribute(megnet_edge_kernel,
                         cudaFuncAttributeMaxDynamicSharedMemorySize, SMEM_TOTAL);
    megnet_edge_kernel<<<grid, NTHR, SMEM_TOTAL>>>(src, dst, ea, u, bat,
                                                   W1, b1, W2, b2, out, E, NT);
    (void)n_in; (void)out_size;
}